// round 14
// baseline (speedup 1.0000x reference)
#include <cuda_runtime.h>
#include <cstdint>

#define T_STEPS 512
#define BATCH   2048
#define F_IN    64
#define HID     32
#define NGATE   128   // 4*HID
#define PFD     3     // recur prefetch distance (steps)

#define NCONS_CTA 256                        // consumer CTAs (4 warps each)
#define NTILES    ((T_STEPS * BATCH) / 64)   // 16384 producer tiles

typedef unsigned long long ull;

// x_proj scratch, CELL-MAJOR gate quads [t][b][cell*4+gtype], padded 4 steps.
__device__ float g_xproj[(size_t)(T_STEPS + 4) * BATCH * NGATE];
__device__ unsigned int g_done[T_STEPS];   // 32 tiles per timestep

__device__ __forceinline__ ull pack2(float lo, float hi) {
    ull r;
    asm("mov.b64 %0, {%1,%2};" : "=l"(r) : "f"(lo), "f"(hi));
    return r;
}
__device__ __forceinline__ void unpack2(ull p, float &lo, float &hi) {
    asm("mov.b64 {%0,%1}, %2;" : "=f"(lo), "=f"(hi) : "l"(p));
}
__device__ __forceinline__ ull fma2(ull a, ull b, ull c) {
    ull d;
    asm("fma.rn.f32x2 %0, %1, %2, %3;" : "=l"(d) : "l"(a), "l"(b), "l"(c));
    return d;
}
__device__ __forceinline__ float tanh_fast(float x) {
    float y;
    asm("tanh.approx.f32 %0, %1;" : "=f"(y) : "f"(x));
    return y;
}
__device__ __forceinline__ float sigm_fast(float x) {
    return fmaf(0.5f, tanh_fast(0.5f * x), 0.5f);
}
__device__ __forceinline__ void cp16(void* smem, const void* gmem) {
    uint32_t s = (uint32_t)__cvta_generic_to_shared(smem);
    asm volatile("cp.async.cg.shared.global [%0], [%1], 16;" :: "r"(s), "l"(gmem));
}
__device__ __forceinline__ unsigned int ld_acq(const unsigned int* p) {
    unsigned int v;
    asm volatile("ld.acquire.gpu.u32 %0, [%1];" : "=r"(v) : "l"(p) : "memory");
    return v;
}

// smem sizing: producer 8s x 8g tile
#define XS    64
#define XPIT  34      // x row pitch (ull)
#define WPIT2 35      // w row pitch (ull), odd -> conflict-free LDS.64
#define SMEM_DYN ((NGATE * WPIT2 + XS * XPIT) * 8)   // 53248 B
#define CONS_WARP_B 4608                             // 4KB ring + 512B hp

__global__ void zero_flags_kernel() {
    if (threadIdx.x < T_STEPS) g_done[threadIdx.x] = 0u;
}

// ============================================================================
// Fused kernel, 128-thread CTAs (3 slots/SM under launch_bounds(128,3)).
// bid <  NCONS_CTA : consumer — 4 independent recur warps (R9 code + flag poll)
// bid >= NCONS_CTA : producer — one 64-sample x_proj tile (R13 8s x 8g code)
// ============================================================================
__global__ void __launch_bounds__(128, 3)
fused_kernel(const float* __restrict__ x,
             const float* __restrict__ W_ih,
             const float* __restrict__ b_ih,
             const float* __restrict__ b_hh,
             const float* __restrict__ W_hh,
             const float* __restrict__ W_d,
             const float* __restrict__ b_d,
             float* __restrict__ out)
{
    extern __shared__ __align__(16) char dynsm[];
    const int t = threadIdx.x;

    if (blockIdx.x >= NCONS_CTA) {
        // ==================== PRODUCER ====================
        ull* wrow = reinterpret_cast<ull*>(dynsm);          // [NGATE][WPIT2]
        ull* xrow = wrow + NGATE * WPIT2;                   // [XS][XPIT]

        const int tile = blockIdx.x - NCONS_CTA;            // 0..16383
        const int tx = t & 15;                              // gates tx+16p
        const int ty = t >> 4;                              // samples ty*8..+7
        const size_t row0 = (size_t)tile * XS;
        const int tstep = tile >> 5;

        // stage W coalesced (8B stores, odd pitch)
        {
            const float4* wg = reinterpret_cast<const float4*>(W_ih);
#pragma unroll
            for (int i = 0; i < 16; i++) {
                const int idx = t + 128 * i;
                const int g = idx >> 4;
                const int c = idx & 15;
                const float4 v = wg[idx];
                float2* dst = reinterpret_cast<float2*>(&wrow[g * WPIT2 + 2 * c]);
                dst[0] = make_float2(v.x, v.y);
                dst[1] = make_float2(v.z, v.w);
            }
        }
        // stage x tile coalesced
        {
            const float4* xg = reinterpret_cast<const float4*>(x + row0 * F_IN);
#pragma unroll
            for (int i = 0; i < 8; i++) {
                const int idx = t + 128 * i;
                const int s = idx >> 4;
                const int c = idx & 15;
                *reinterpret_cast<float4*>(&xrow[s * XPIT + 2 * c]) = xg[idx];
            }
        }

        ull acc[8][8];
#pragma unroll
        for (int p = 0; p < 8; p++) {
            const int g = tx + 16 * p;
            const ull b = pack2(b_ih[g] + b_hh[g], 0.0f);
#pragma unroll
            for (int q = 0; q < 8; q++) acc[q][p] = b;
        }
        __syncthreads();

#pragma unroll 4
        for (int kk = 0; kk < 32; kk++) {
            ull xv[8], wv[8];
#pragma unroll
            for (int q = 0; q < 8; q++)
                xv[q] = xrow[(ty * 8 + q) * XPIT + kk];
#pragma unroll
            for (int p = 0; p < 8; p++)
                wv[p] = wrow[(tx + 16 * p) * WPIT2 + kk];
#pragma unroll
            for (int q = 0; q < 8; q++)
#pragma unroll
                for (int p = 0; p < 8; p++)
                    acc[q][p] = fma2(xv[q], wv[p], acc[q][p]);
        }

        // writeout: cell-major gate quads
#pragma unroll
        for (int q = 0; q < 8; q++) {
            float hlo, hhi;
            float4 v0, v1;
            unpack2(acc[q][0], hlo, hhi); v0.x = hlo + hhi;
            unpack2(acc[q][2], hlo, hhi); v0.y = hlo + hhi;
            unpack2(acc[q][4], hlo, hhi); v0.z = hlo + hhi;
            unpack2(acc[q][6], hlo, hhi); v0.w = hlo + hhi;
            unpack2(acc[q][1], hlo, hhi); v1.x = hlo + hhi;
            unpack2(acc[q][3], hlo, hhi); v1.y = hlo + hhi;
            unpack2(acc[q][5], hlo, hhi); v1.z = hlo + hhi;
            unpack2(acc[q][7], hlo, hhi); v1.w = hlo + hhi;
            float4* op4 = reinterpret_cast<float4*>(
                g_xproj + (row0 + ty * 8 + q) * NGATE);
            op4[tx]      = v0;
            op4[tx + 16] = v1;
        }

        __threadfence();
        __syncthreads();
        if (t == 0) atomicAdd(&g_done[tstep], 1u);
        return;
    }

    // ==================== CONSUMER: 4 independent recur warps ====================
    const int warp = t >> 5;
    const int lane = t & 31;
    const int gw   = blockIdx.x * 4 + warp;     // global warp 0..1023
    const int bA   = gw * 2;                    // samples bA, bA+1

    char* wbase = dynsm + warp * CONS_WARP_B;
    float4 (*xring)[2][32] = reinterpret_cast<float4(*)[2][32]>(wbase);
    ull* hp = reinterpret_cast<ull*>(wbase + 4096);   // [buf][sample][kpair]

    ull wI[16], wF[16], wG[16], wO[16];
    {
        const ull* wr = reinterpret_cast<const ull*>(W_hh);
#pragma unroll
        for (int kk = 0; kk < 16; kk++) {
            wI[kk] = wr[(lane)      * 16 + kk];
            wF[kk] = wr[(lane + 32) * 16 + kk];
            wG[kk] = wr[(lane + 64) * 16 + kk];
            wO[kk] = wr[(lane + 96) * 16 + kk];
        }
    }

    if (lane < 16) { hp[lane] = 0ULL; hp[16 + lane] = 0ULL; }
    float cA = 0.0f, cB = 0.0f;

    const float4* gxA = reinterpret_cast<const float4*>(
        g_xproj + (size_t)bA * NGATE) + lane;
    const float4* gxB = gxA + NGATE / 4;
    const size_t s4 = (size_t)BATCH * NGATE / 4;

    auto wait_step = [&](int q) {
        q = q < T_STEPS ? q : T_STEPS - 1;
        if (lane == 0) {
            while (ld_acq(&g_done[q]) < 32u) __nanosleep(256);
        }
        __syncwarp();
    };

#pragma unroll
    for (int i = 0; i < PFD; i++) {
        wait_step(i);
        cp16(&xring[i][0][lane], gxA + (size_t)i * s4);
        cp16(&xring[i][1][lane], gxB + (size_t)i * s4);
        asm volatile("cp.async.commit_group;");
    }

#pragma unroll 1
    for (int ts0 = 0; ts0 < T_STEPS; ts0 += 4) {
#pragma unroll
        for (int u = 0; u < 4; u++) {
            const int ts = ts0 + u;
            const int slot = (ts + PFD) & 3;
            wait_step(ts + PFD);
            cp16(&xring[slot][0][lane], gxA + (size_t)(ts + PFD) * s4);
            cp16(&xring[slot][1][lane], gxB + (size_t)(ts + PFD) * s4);
            asm volatile("cp.async.commit_group;");
            asm volatile("cp.async.wait_group 3;");

            const float4 curA = xring[ts & 3][0][lane];
            const float4 curB = xring[ts & 3][1][lane];
            const int rb = ts & 1;
            const ulonglong2* hqA = reinterpret_cast<const ulonglong2*>(hp + rb * 32);
            const ulonglong2* hqB = reinterpret_cast<const ulonglong2*>(hp + rb * 32 + 16);

            ull aIA = pack2(curA.x, 0.0f), aFA = pack2(curA.y, 0.0f);
            ull aGA = pack2(curA.z, 0.0f), aOA = pack2(curA.w, 0.0f);
            ull aIB = pack2(curB.x, 0.0f), aFB = pack2(curB.y, 0.0f);
            ull aGB = pack2(curB.z, 0.0f), aOB = pack2(curB.w, 0.0f);
#pragma unroll
            for (int k2 = 0; k2 < 8; k2++) {
                const ulonglong2 hvA = hqA[k2];
                const ulonglong2 hvB = hqB[k2];
                aIA = fma2(hvA.x, wI[2 * k2], aIA);
                aIB = fma2(hvB.x, wI[2 * k2], aIB);
                aFA = fma2(hvA.x, wF[2 * k2], aFA);
                aFB = fma2(hvB.x, wF[2 * k2], aFB);
                aGA = fma2(hvA.x, wG[2 * k2], aGA);
                aGB = fma2(hvB.x, wG[2 * k2], aGB);
                aOA = fma2(hvA.x, wO[2 * k2], aOA);
                aOB = fma2(hvB.x, wO[2 * k2], aOB);
                aIA = fma2(hvA.y, wI[2 * k2 + 1], aIA);
                aIB = fma2(hvB.y, wI[2 * k2 + 1], aIB);
                aFA = fma2(hvA.y, wF[2 * k2 + 1], aFA);
                aFB = fma2(hvB.y, wF[2 * k2 + 1], aFB);
                aGA = fma2(hvA.y, wG[2 * k2 + 1], aGA);
                aGB = fma2(hvB.y, wG[2 * k2 + 1], aGB);
                aOA = fma2(hvA.y, wO[2 * k2 + 1], aOA);
                aOB = fma2(hvB.y, wO[2 * k2 + 1], aOB);
            }
            float lo, hi;
            unpack2(aIA, lo, hi); const float igA = sigm_fast(lo + hi);
            unpack2(aIB, lo, hi); const float igB = sigm_fast(lo + hi);
            unpack2(aFA, lo, hi); const float fgA = sigm_fast(lo + hi);
            unpack2(aFB, lo, hi); const float fgB = sigm_fast(lo + hi);
            unpack2(aGA, lo, hi); const float ggA = tanh_fast(lo + hi);
            unpack2(aGB, lo, hi); const float ggB = tanh_fast(lo + hi);
            unpack2(aOA, lo, hi); const float ogA = sigm_fast(lo + hi);
            unpack2(aOB, lo, hi); const float ogB = sigm_fast(lo + hi);

            cA = fgA * cA + igA * ggA;
            cB = fgB * cB + igB * ggB;
            const float hA = ogA * tanh_fast(cA);
            const float hB = ogB * tanh_fast(cB);
            reinterpret_cast<float*>(hp + (1 - rb) * 32)[lane]      = hA;
            reinterpret_cast<float*>(hp + (1 - rb) * 32 + 16)[lane] = hB;

            __syncwarp();
        }
    }

    if ((lane & 3) < 3 && lane < 8) {
        const int s = lane >> 2;
        const int a = lane & 3;
        float sum = b_d[a];
        const float* hf = reinterpret_cast<const float*>(
            hp + (T_STEPS & 1) * 32 + s * 16);
#pragma unroll
        for (int j = 0; j < HID; j++)
            sum += fmaxf(hf[j], 0.0f) * W_d[a * HID + j];
        out[(size_t)(bA + s) * 3 + a] = sum;
    }
}

extern "C" void kernel_launch(void* const* d_in, const int* in_sizes, int n_in,
                              void* d_out, int out_size)
{
    const float* x    = (const float*)d_in[0];
    const float* W_ih = (const float*)d_in[1];
    const float* W_hh = (const float*)d_in[2];
    const float* b_ih = (const float*)d_in[3];
    const float* b_hh = (const float*)d_in[4];
    const float* W_d  = (const float*)d_in[5];
    const float* b_d  = (const float*)d_in[6];
    float* out = (float*)d_out;

    cudaFuncSetAttribute(fused_kernel,
                         cudaFuncAttributeMaxDynamicSharedMemorySize, SMEM_DYN);

    zero_flags_kernel<<<1, T_STEPS>>>();
    fused_kernel<<<NCONS_CTA + NTILES, 128, SMEM_DYN>>>(
        x, W_ih, b_ih, b_hh, W_hh, W_d, b_d, out);
}

// round 15
// speedup vs baseline: 1.1912x; 1.1912x over previous
#include <cuda_runtime.h>
#include <cstdint>

#define T_STEPS 512
#define BATCH   2048
#define F_IN    64
#define HID     32
#define NGATE   128   // 4*HID
#define PFD     3     // recur prefetch distance (steps)
#define NSW     4     // samples per recur warp

typedef unsigned long long ull;

// x_proj scratch, CELL-MAJOR gate quads [t][b][cell*4+gtype], padded 4 steps.
__device__ float g_xproj[(size_t)(T_STEPS + 4) * BATCH * NGATE];

__device__ __forceinline__ ull pack2(float lo, float hi) {
    ull r;
    asm("mov.b64 %0, {%1,%2};" : "=l"(r) : "f"(lo), "f"(hi));
    return r;
}
__device__ __forceinline__ void unpack2(ull p, float &lo, float &hi) {
    asm("mov.b64 {%0,%1}, %2;" : "=f"(lo), "=f"(hi) : "l"(p));
}
__device__ __forceinline__ ull fma2(ull a, ull b, ull c) {
    ull d;
    asm("fma.rn.f32x2 %0, %1, %2, %3;" : "=l"(d) : "l"(a), "l"(b), "l"(c));
    return d;
}
__device__ __forceinline__ float tanh_fast(float x) {
    float y;
    asm("tanh.approx.f32 %0, %1;" : "=f"(y) : "f"(x));
    return y;
}
__device__ __forceinline__ float sigm_fast(float x) {
    return fmaf(0.5f, tanh_fast(0.5f * x), 0.5f);
}
__device__ __forceinline__ void cp16(void* smem, const void* gmem) {
    uint32_t s = (uint32_t)__cvta_generic_to_shared(smem);
    asm volatile("cp.async.cg.shared.global [%0], [%1], 16;" :: "r"(s), "l"(gmem));
}

// ============================================================================
// Kernel A: x_proj = x @ W_ih^T + (b_ih + b_hh)   -- [1M, 64] x [64, 128]
// 128-thread CTA, TWO 64-sample sub-tiles per CTA (W staged once, 1 barrier).
// Thread tile 8s x 8g, per kk: 16 LDS.64 feed 64 FFMA2. 3 CTAs/SM.
// ============================================================================
#define XS    64      // samples per sub-tile
#define XPIT  34      // x row pitch (ull)
#define WPIT2 35      // w row pitch (ull), odd -> conflict-free LDS.64
#define SMEM_X ((NGATE * WPIT2 + 2 * XS * XPIT) * 8)   // 70656 B

__global__ void __launch_bounds__(128, 3)
xproj_kernel(const float* __restrict__ x,
             const float* __restrict__ W_ih,
             const float* __restrict__ b_ih,
             const float* __restrict__ b_hh)
{
    extern __shared__ __align__(16) ull sm2[];
    ull* wrow  = sm2;                               // [NGATE][WPIT2]
    ull* xtile = sm2 + NGATE * WPIT2;               // [2][XS][XPIT]

    const int t  = threadIdx.x;
    const int tx = t & 15;               // gates: tx + 16p, p=0..7
    const int ty = t >> 4;               // samples: ty*8 .. ty*8+7
    const size_t row0 = (size_t)blockIdx.x * (2 * XS);

    // ---- stage W (32 KB) once, coalesced (8B stores, odd pitch) ----
    {
        const float4* wg = reinterpret_cast<const float4*>(W_ih);
#pragma unroll
        for (int i = 0; i < 16; i++) {
            const int idx = t + 128 * i;
            const int g = idx >> 4;
            const int c = idx & 15;
            const float4 v = wg[idx];
            float2* dst = reinterpret_cast<float2*>(&wrow[g * WPIT2 + 2 * c]);
            dst[0] = make_float2(v.x, v.y);
            dst[1] = make_float2(v.z, v.w);
        }
    }
    // ---- stage BOTH x sub-tiles (32 KB), coalesced ----
    {
        const float4* xg = reinterpret_cast<const float4*>(x + row0 * F_IN);
#pragma unroll
        for (int i = 0; i < 16; i++) {
            const int idx = t + 128 * i;            // float4 id, 0..2047
            const int s = idx >> 4;                 // 0..127
            const int c = idx & 15;
            const int h = s >> 6;                   // sub-tile
            const int sl = s & 63;
            *reinterpret_cast<float4*>(
                &xtile[(h * XS + sl) * XPIT + 2 * c]) = xg[idx];
        }
    }
    // bias
    float bf[8];
#pragma unroll
    for (int p = 0; p < 8; p++) {
        const int g = tx + 16 * p;
        bf[p] = b_ih[g] + b_hh[g];
    }
    __syncthreads();

#pragma unroll 1
    for (int half = 0; half < 2; half++) {
        const ull* xr = xtile + half * XS * XPIT;

        ull acc[8][8];
#pragma unroll
        for (int p = 0; p < 8; p++) {
            const ull b = pack2(bf[p], 0.0f);
#pragma unroll
            for (int q = 0; q < 8; q++) acc[q][p] = b;
        }

#pragma unroll 4
        for (int kk = 0; kk < 32; kk++) {
            ull xv[8], wv[8];
#pragma unroll
            for (int q = 0; q < 8; q++)
                xv[q] = xr[(ty * 8 + q) * XPIT + kk];
#pragma unroll
            for (int p = 0; p < 8; p++)
                wv[p] = wrow[(tx + 16 * p) * WPIT2 + kk];
#pragma unroll
            for (int q = 0; q < 8; q++)
#pragma unroll
                for (int p = 0; p < 8; p++)
                    acc[q][p] = fma2(xv[q], wv[p], acc[q][p]);
        }

        // writeout: cell-major gate quads, coalesced STG.128
        const size_t rbase = row0 + half * XS;
#pragma unroll
        for (int q = 0; q < 8; q++) {
            float hlo, hhi;
            float4 v0, v1;
            unpack2(acc[q][0], hlo, hhi); v0.x = hlo + hhi;   // i, cell tx
            unpack2(acc[q][2], hlo, hhi); v0.y = hlo + hhi;   // f
            unpack2(acc[q][4], hlo, hhi); v0.z = hlo + hhi;   // g
            unpack2(acc[q][6], hlo, hhi); v0.w = hlo + hhi;   // o
            unpack2(acc[q][1], hlo, hhi); v1.x = hlo + hhi;   // cell tx+16
            unpack2(acc[q][3], hlo, hhi); v1.y = hlo + hhi;
            unpack2(acc[q][5], hlo, hhi); v1.z = hlo + hhi;
            unpack2(acc[q][7], hlo, hhi); v1.w = hlo + hhi;
            float4* op4 = reinterpret_cast<float4*>(
                g_xproj + (rbase + ty * 8 + q) * NGATE);
            op4[tx]      = v0;
            op4[tx + 16] = v1;
        }
    }
}

// ============================================================================
// Kernel B: recurrence, single-warp CTA, FOUR samples per warp (512 warps).
// 4 independent dependency chains per warp; weights shared in registers.
// cp.async 4-slot ring per sample; syncwarp-only.
// ============================================================================
__global__ void __launch_bounds__(32)
recur_kernel(const float* __restrict__ W_hh,
             const float* __restrict__ W_d,
             const float* __restrict__ b_d,
             float* __restrict__ out)
{
    __shared__ __align__(16) float4 xring[4][NSW][32];   // 8 KB
    __shared__ ull hp[2][NSW][HID / 2];                  // 1 KB

    const int t  = threadIdx.x;         // lane = cell index
    const int b0 = blockIdx.x * NSW;    // samples b0..b0+3

    ull wI[16], wF[16], wG[16], wO[16];
    {
        const ull* wr = reinterpret_cast<const ull*>(W_hh);
#pragma unroll
        for (int kk = 0; kk < 16; kk++) {
            wI[kk] = wr[(t)      * 16 + kk];
            wF[kk] = wr[(t + 32) * 16 + kk];
            wG[kk] = wr[(t + 64) * 16 + kk];
            wO[kk] = wr[(t + 96) * 16 + kk];
        }
    }

    if (t < 16) {
#pragma unroll
        for (int s = 0; s < NSW; s++) hp[0][s][t] = 0ULL;
    }
    float c[NSW] = {0.0f, 0.0f, 0.0f, 0.0f};

    const float4* gx0 = reinterpret_cast<const float4*>(
        g_xproj + (size_t)b0 * NGATE) + t;
    const size_t s4 = (size_t)BATCH * NGATE / 4;   // float4 step stride

#pragma unroll
    for (int i = 0; i < PFD; i++) {
#pragma unroll
        for (int s = 0; s < NSW; s++)
            cp16(&xring[i][s][t], gx0 + (size_t)i * s4 + s * (NGATE / 4));
        asm volatile("cp.async.commit_group;");
    }
    __syncwarp();

#pragma unroll 1
    for (int ts0 = 0; ts0 < T_STEPS; ts0 += 4) {
#pragma unroll
        for (int u = 0; u < 4; u++) {
            const int ts = ts0 + u;
            const int slot = (ts + PFD) & 3;
#pragma unroll
            for (int s = 0; s < NSW; s++)
                cp16(&xring[slot][s][t],
                     gx0 + (size_t)(ts + PFD) * s4 + s * (NGATE / 4));
            asm volatile("cp.async.commit_group;");
            asm volatile("cp.async.wait_group 3;");

            const int rb = ts & 1;
            float4 cur[NSW];
            ull a[NSW][4];
#pragma unroll
            for (int s = 0; s < NSW; s++) {
                cur[s] = xring[ts & 3][s][t];
                a[s][0] = pack2(cur[s].x, 0.0f);
                a[s][1] = pack2(cur[s].y, 0.0f);
                a[s][2] = pack2(cur[s].z, 0.0f);
                a[s][3] = pack2(cur[s].w, 0.0f);
            }

#pragma unroll
            for (int k2 = 0; k2 < 8; k2++) {
#pragma unroll
                for (int s = 0; s < NSW; s++) {
                    const ulonglong2 hv = *reinterpret_cast<const ulonglong2*>(
                        &hp[rb][s][2 * k2]);
                    a[s][0] = fma2(hv.x, wI[2 * k2], a[s][0]);
                    a[s][1] = fma2(hv.x, wF[2 * k2], a[s][1]);
                    a[s][2] = fma2(hv.x, wG[2 * k2], a[s][2]);
                    a[s][3] = fma2(hv.x, wO[2 * k2], a[s][3]);
                    a[s][0] = fma2(hv.y, wI[2 * k2 + 1], a[s][0]);
                    a[s][1] = fma2(hv.y, wF[2 * k2 + 1], a[s][1]);
                    a[s][2] = fma2(hv.y, wG[2 * k2 + 1], a[s][2]);
                    a[s][3] = fma2(hv.y, wO[2 * k2 + 1], a[s][3]);
                }
            }

#pragma unroll
            for (int s = 0; s < NSW; s++) {
                float lo, hi;
                unpack2(a[s][0], lo, hi); const float ig = sigm_fast(lo + hi);
                unpack2(a[s][1], lo, hi); const float fg = sigm_fast(lo + hi);
                unpack2(a[s][2], lo, hi); const float gg = tanh_fast(lo + hi);
                unpack2(a[s][3], lo, hi); const float og = sigm_fast(lo + hi);
                c[s] = fg * c[s] + ig * gg;
                const float h = og * tanh_fast(c[s]);
                reinterpret_cast<float*>(hp[1 - rb][s])[t] = h;
            }

            __syncwarp();
        }
    }

    // epilogue: out[b, a] = relu(h_T) @ W_d^T + b_d  (final h in hp[0])
    if (t < NSW * 3) {
        const int s = t / 3;
        const int a = t % 3;
        float sum = b_d[a];
        const float* hf = reinterpret_cast<const float*>(hp[T_STEPS & 1][s]);
#pragma unroll
        for (int j = 0; j < HID; j++)
            sum += fmaxf(hf[j], 0.0f) * W_d[a * HID + j];
        out[(size_t)(b0 + s) * 3 + a] = sum;
    }
}

extern "C" void kernel_launch(void* const* d_in, const int* in_sizes, int n_in,
                              void* d_out, int out_size)
{
    const float* x    = (const float*)d_in[0];
    const float* W_ih = (const float*)d_in[1];
    const float* W_hh = (const float*)d_in[2];
    const float* b_ih = (const float*)d_in[3];
    const float* b_hh = (const float*)d_in[4];
    const float* W_d  = (const float*)d_in[5];
    const float* b_d  = (const float*)d_in[6];
    float* out = (float*)d_out;

    cudaFuncSetAttribute(xproj_kernel,
                         cudaFuncAttributeMaxDynamicSharedMemorySize, SMEM_X);

    // Kernel A: x_proj GEMM (8192 CTAs, 2 sub-tiles each)
    {
        dim3 grid((T_STEPS * BATCH) / (2 * XS));   // 8192
        dim3 block(128);
        xproj_kernel<<<grid, block, SMEM_X>>>(x, W_ih, b_ih, b_hh);
    }
    // Kernel B: sequential LSTM recurrence + decode head
    {
        dim3 grid(BATCH / NSW);                    // 512 single-warp CTAs
        dim3 block(32);
        recur_kernel<<<grid, block>>>(W_hh, W_d, b_d, out);
    }
}

// round 16
// speedup vs baseline: 1.5196x; 1.2757x over previous
#include <cuda_runtime.h>
#include <cstdint>

#define T_STEPS 512
#define BATCH   2048
#define F_IN    64
#define HID     32
#define NGATE   128   // 4*HID
#define PFD     3     // recur prefetch distance (steps)
#define NSW     4     // samples per recur warp

typedef unsigned long long ull;

// x_proj scratch, CELL-MAJOR gate quads [t][b][cell*4+gtype], padded 4 steps.
__device__ float g_xproj[(size_t)(T_STEPS + 4) * BATCH * NGATE];

__device__ __forceinline__ ull pack2(float lo, float hi) {
    ull r;
    asm("mov.b64 %0, {%1,%2};" : "=l"(r) : "f"(lo), "f"(hi));
    return r;
}
__device__ __forceinline__ void unpack2(ull p, float &lo, float &hi) {
    asm("mov.b64 {%0,%1}, %2;" : "=f"(lo), "=f"(hi) : "l"(p));
}
__device__ __forceinline__ ull fma2(ull a, ull b, ull c) {
    ull d;
    asm("fma.rn.f32x2 %0, %1, %2, %3;" : "=l"(d) : "l"(a), "l"(b), "l"(c));
    return d;
}
__device__ __forceinline__ float tanh_fast(float x) {
    float y;
    asm("tanh.approx.f32 %0, %1;" : "=f"(y) : "f"(x));
    return y;
}
__device__ __forceinline__ float sigm_fast(float x) {
    return fmaf(0.5f, tanh_fast(0.5f * x), 0.5f);
}
__device__ __forceinline__ void cp16(void* smem, const void* gmem) {
    uint32_t s = (uint32_t)__cvta_generic_to_shared(smem);
    asm volatile("cp.async.cg.shared.global [%0], [%1], 16;" :: "r"(s), "l"(gmem));
}

// ============================================================================
// Kernel A: x_proj = x @ W_ih^T + (b_ih + b_hh)   -- [1M, 64] x [64, 128]
// R13 version (best measured ~367us): 128-thread CTA, one 64-sample tile,
// thread tile 8s x 8g, per kk: 16 LDS.64 feed 64 FFMA2, 3 CTAs/SM.
// ============================================================================
#define XS    64     // samples per tile
#define XPIT  34     // x row pitch (ull)
#define WPIT2 35     // w row pitch (ull): odd -> conflict-free LDS.64

__global__ void __launch_bounds__(128, 3)
xproj_kernel(const float* __restrict__ x,
             const float* __restrict__ W_ih,
             const float* __restrict__ b_ih,
             const float* __restrict__ b_hh)
{
    __shared__ __align__(16) ull wrow[NGATE * WPIT2];   // 35840 B
    __shared__ __align__(16) ull xrow[XS * XPIT];       // 17408 B

    const int t  = threadIdx.x;
    const int tx = t & 15;               // gates: tx + 16p, p=0..7
    const int ty = t >> 4;               // samples: ty*8 .. ty*8+7
    const size_t row0 = (size_t)blockIdx.x * XS;

    // ---- stage W (32 KB) coalesced: 16 float4/thread, 8B stores (odd pitch)
    {
        const float4* wg = reinterpret_cast<const float4*>(W_ih);
#pragma unroll
        for (int i = 0; i < 16; i++) {
            const int idx = t + 128 * i;      // float4 index, g-major
            const int g = idx >> 4;
            const int c = idx & 15;
            const float4 v = wg[idx];
            float2* dst = reinterpret_cast<float2*>(&wrow[g * WPIT2 + 2 * c]);
            dst[0] = make_float2(v.x, v.y);
            dst[1] = make_float2(v.z, v.w);
        }
    }
    // ---- stage x tile (16 KB) coalesced: 8 float4/thread ----
    {
        const float4* xg = reinterpret_cast<const float4*>(x + row0 * F_IN);
#pragma unroll
        for (int i = 0; i < 8; i++) {
            const int idx = t + 128 * i;
            const int s = idx >> 4;
            const int c = idx & 15;
            *reinterpret_cast<float4*>(&xrow[s * XPIT + 2 * c]) = xg[idx];
        }
    }

    // ---- acc init with bias in lo lane: 8 samples x 8 gates ----
    ull acc[8][8];
    {
#pragma unroll
        for (int p = 0; p < 8; p++) {
            const int g = tx + 16 * p;
            const ull b = pack2(b_ih[g] + b_hh[g], 0.0f);
#pragma unroll
            for (int q = 0; q < 8; q++) acc[q][p] = b;
        }
    }
    __syncthreads();

    // ---- main loop: per kk: 16 LDS.64 feed 64 FFMA2 ----
#pragma unroll 4
    for (int kk = 0; kk < 32; kk++) {
        ull xv[8], wv[8];
#pragma unroll
        for (int q = 0; q < 8; q++)
            xv[q] = xrow[(ty * 8 + q) * XPIT + kk];
#pragma unroll
        for (int p = 0; p < 8; p++)
            wv[p] = wrow[(tx + 16 * p) * WPIT2 + kk];
#pragma unroll
        for (int q = 0; q < 8; q++)
#pragma unroll
            for (int p = 0; p < 8; p++)
                acc[q][p] = fma2(xv[q], wv[p], acc[q][p]);
    }

    // ---- writeout: cell-major gate quads, coalesced STG.128 ----
#pragma unroll
    for (int q = 0; q < 8; q++) {
        float hlo, hhi;
        float4 v0, v1;
        unpack2(acc[q][0], hlo, hhi); v0.x = hlo + hhi;   // i, cell tx
        unpack2(acc[q][2], hlo, hhi); v0.y = hlo + hhi;   // f
        unpack2(acc[q][4], hlo, hhi); v0.z = hlo + hhi;   // g
        unpack2(acc[q][6], hlo, hhi); v0.w = hlo + hhi;   // o
        unpack2(acc[q][1], hlo, hhi); v1.x = hlo + hhi;   // cell tx+16
        unpack2(acc[q][3], hlo, hhi); v1.y = hlo + hhi;
        unpack2(acc[q][5], hlo, hhi); v1.z = hlo + hhi;
        unpack2(acc[q][7], hlo, hhi); v1.w = hlo + hhi;
        float4* op4 = reinterpret_cast<float4*>(
            g_xproj + (row0 + ty * 8 + q) * NGATE);
        op4[tx]      = v0;
        op4[tx + 16] = v1;
    }
}

// ============================================================================
// Kernel B: recurrence, R15 version (best measured 235us): single-warp CTA,
// FOUR samples per warp (512 warps), cp.async 4-slot ring, syncwarp-only.
// ============================================================================
__global__ void __launch_bounds__(32)
recur_kernel(const float* __restrict__ W_hh,
             const float* __restrict__ W_d,
             const float* __restrict__ b_d,
             float* __restrict__ out)
{
    __shared__ __align__(16) float4 xring[4][NSW][32];   // 8 KB
    __shared__ ull hp[2][NSW][HID / 2];                  // 1 KB

    const int t  = threadIdx.x;         // lane = cell index
    const int b0 = blockIdx.x * NSW;    // samples b0..b0+3

    ull wI[16], wF[16], wG[16], wO[16];
    {
        const ull* wr = reinterpret_cast<const ull*>(W_hh);
#pragma unroll
        for (int kk = 0; kk < 16; kk++) {
            wI[kk] = wr[(t)      * 16 + kk];
            wF[kk] = wr[(t + 32) * 16 + kk];
            wG[kk] = wr[(t + 64) * 16 + kk];
            wO[kk] = wr[(t + 96) * 16 + kk];
        }
    }

    if (t < 16) {
#pragma unroll
        for (int s = 0; s < NSW; s++) hp[0][s][t] = 0ULL;
    }
    float c[NSW] = {0.0f, 0.0f, 0.0f, 0.0f};

    const float4* gx0 = reinterpret_cast<const float4*>(
        g_xproj + (size_t)b0 * NGATE) + t;
    const size_t s4 = (size_t)BATCH * NGATE / 4;   // float4 step stride

#pragma unroll
    for (int i = 0; i < PFD; i++) {
#pragma unroll
        for (int s = 0; s < NSW; s++)
            cp16(&xring[i][s][t], gx0 + (size_t)i * s4 + s * (NGATE / 4));
        asm volatile("cp.async.commit_group;");
    }
    __syncwarp();

#pragma unroll 1
    for (int ts0 = 0; ts0 < T_STEPS; ts0 += 4) {
#pragma unroll
        for (int u = 0; u < 4; u++) {
            const int ts = ts0 + u;
            const int slot = (ts + PFD) & 3;
#pragma unroll
            for (int s = 0; s < NSW; s++)
                cp16(&xring[slot][s][t],
                     gx0 + (size_t)(ts + PFD) * s4 + s * (NGATE / 4));
            asm volatile("cp.async.commit_group;");
            asm volatile("cp.async.wait_group 3;");

            const int rb = ts & 1;
            float4 cur[NSW];
            ull a[NSW][4];
#pragma unroll
            for (int s = 0; s < NSW; s++) {
                cur[s] = xring[ts & 3][s][t];
                a[s][0] = pack2(cur[s].x, 0.0f);
                a[s][1] = pack2(cur[s].y, 0.0f);
                a[s][2] = pack2(cur[s].z, 0.0f);
                a[s][3] = pack2(cur[s].w, 0.0f);
            }

#pragma unroll
            for (int k2 = 0; k2 < 8; k2++) {
#pragma unroll
                for (int s = 0; s < NSW; s++) {
                    const ulonglong2 hv = *reinterpret_cast<const ulonglong2*>(
                        &hp[rb][s][2 * k2]);
                    a[s][0] = fma2(hv.x, wI[2 * k2], a[s][0]);
                    a[s][1] = fma2(hv.x, wF[2 * k2], a[s][1]);
                    a[s][2] = fma2(hv.x, wG[2 * k2], a[s][2]);
                    a[s][3] = fma2(hv.x, wO[2 * k2], a[s][3]);
                    a[s][0] = fma2(hv.y, wI[2 * k2 + 1], a[s][0]);
                    a[s][1] = fma2(hv.y, wF[2 * k2 + 1], a[s][1]);
                    a[s][2] = fma2(hv.y, wG[2 * k2 + 1], a[s][2]);
                    a[s][3] = fma2(hv.y, wO[2 * k2 + 1], a[s][3]);
                }
            }

#pragma unroll
            for (int s = 0; s < NSW; s++) {
                float lo, hi;
                unpack2(a[s][0], lo, hi); const float ig = sigm_fast(lo + hi);
                unpack2(a[s][1], lo, hi); const float fg = sigm_fast(lo + hi);
                unpack2(a[s][2], lo, hi); const float gg = tanh_fast(lo + hi);
                unpack2(a[s][3], lo, hi); const float og = sigm_fast(lo + hi);
                c[s] = fg * c[s] + ig * gg;
                const float h = og * tanh_fast(c[s]);
                reinterpret_cast<float*>(hp[1 - rb][s])[t] = h;
            }

            __syncwarp();
        }
    }

    // epilogue: out[b, a] = relu(h_T) @ W_d^T + b_d  (final h in hp[0])
    if (t < NSW * 3) {
        const int s = t / 3;
        const int a = t % 3;
        float sum = b_d[a];
        const float* hf = reinterpret_cast<const float*>(hp[T_STEPS & 1][s]);
#pragma unroll
        for (int j = 0; j < HID; j++)
            sum += fmaxf(hf[j], 0.0f) * W_d[a * HID + j];
        out[(size_t)(b0 + s) * 3 + a] = sum;
    }
}

extern "C" void kernel_launch(void* const* d_in, const int* in_sizes, int n_in,
                              void* d_out, int out_size)
{
    const float* x    = (const float*)d_in[0];
    const float* W_ih = (const float*)d_in[1];
    const float* W_hh = (const float*)d_in[2];
    const float* b_ih = (const float*)d_in[3];
    const float* b_hh = (const float*)d_in[4];
    const float* W_d  = (const float*)d_in[5];
    const float* b_d  = (const float*)d_in[6];
    float* out = (float*)d_out;

    // Kernel A: x_proj GEMM (R13 best variant, 16384 tiles)
    {
        dim3 grid((T_STEPS * BATCH) / XS);   // 16384
        dim3 block(128);
        xproj_kernel<<<grid, block>>>(x, W_ih, b_ih, b_hh);
    }
    // Kernel B: sequential LSTM recurrence + decode head (R15 best variant)
    {
        dim3 grid(BATCH / NSW);              // 512 single-warp CTAs
        dim3 block(32);
        recur_kernel<<<grid, block>>>(W_hh, W_d, b_d, out);
    }
}